// round 14
// baseline (speedup 1.0000x reference)
#include <cuda_runtime.h>
#include <cuda_fp16.h>
#include <cstdint>

typedef __half f16;

#define S_LEN 2048
#define HID   2048
#define QKV_N 3072
#define NH    16
// q scale with log2(e) folded in (flash softmax runs in base-2)
#define QSCALE (0.08838834764831845f * 1.4426950408889634f)

// ---------------- scratch (static device allocations) ----------------
__device__ float g_qkv[S_LEN * QKV_N];
__device__ f16  g_xh[S_LEN * HID];                       // hidden fp16; reused for attn
__device__ f16  g_wh[QKV_N * HID];                       // W_attn^T (fp16)
__device__ f16  g_w2h[HID * HID];                        // W_proj^T (fp16)
__device__ f16  g_qh[S_LEN * HID], g_ql[S_LEN * HID];
__device__ f16  g_kh[S_LEN * 512];
__device__ f16  g_vth[512 * S_LEN];                      // V^T per kv head

// ---------------- helpers ----------------
__device__ __forceinline__ uint32_t smem_u32(const void* p) {
    uint32_t a;
    asm("{ .reg .u64 t; cvta.to.shared.u64 t, %1; cvt.u32.u64 %0, t; }" : "=r"(a) : "l"(p));
    return a;
}
#define CP16(dst, src) \
    asm volatile("cp.async.cg.shared.global [%0], [%1], 16;" :: "r"(dst), "l"(src))
#define CP_COMMIT() asm volatile("cp.async.commit_group;" ::: "memory")
#define CP_WAIT1()  asm volatile("cp.async.wait_group 1;" ::: "memory")
#define CP_WAIT0()  asm volatile("cp.async.wait_group 0;" ::: "memory")

__device__ __forceinline__ void ldsm_x4(uint32_t& r0, uint32_t& r1, uint32_t& r2,
                                        uint32_t& r3, uint32_t a) {
    asm volatile("ldmatrix.sync.aligned.m8n8.x4.shared.b16 {%0,%1,%2,%3}, [%4];"
                 : "=r"(r0), "=r"(r1), "=r"(r2), "=r"(r3) : "r"(a));
}
__device__ __forceinline__ void hmma(float* d, const uint32_t* a, const uint32_t* b) {
    asm volatile("mma.sync.aligned.m16n8k16.row.col.f32.f16.f16.f32 "
                 "{%0,%1,%2,%3}, {%4,%5,%6,%7}, {%8,%9}, {%0,%1,%2,%3};"
                 : "+f"(d[0]), "+f"(d[1]), "+f"(d[2]), "+f"(d[3])
                 : "r"(a[0]), "r"(a[1]), "r"(a[2]), "r"(a[3]), "r"(b[0]), "r"(b[1]));
}
__device__ __forceinline__ float ex2(float x) {
    float r; asm("ex2.approx.f32 %0, %1;" : "=f"(r) : "f"(x)); return r;
}
__device__ __forceinline__ uint32_t pack_f16(float lo, float hi) {
    __half2 h = __floats2half2_rn(lo, hi);
    return *reinterpret_cast<uint32_t*>(&h);
}

// ---------------------------------------------------------------------------
// single-term fp16 GEMM via mma.sync: C = A @ B^T, B is [N][K]
// 128 threads, 2x2 warp grid, warp tile 64x64, BM=128, BN=128, BK=32.
// ---------------------------------------------------------------------------
#define TROW    80
#define A_TB    (128 * TROW)           // 10240 B
#define B_TB    (128 * TROW)           // 10240 B
#define STAGE_B (A_TB + B_TB)          // 20480 B
#define GEMM_SMEM (2 * STAGE_B)        // 40960 B

__device__ __forceinline__ void tile_cp_n(const f16* __restrict__ g, int ldg,
                                          int r0, int k0, uint32_t sdst,
                                          int nrows, int t) {
    int nops = nrows * 4;
    for (int o = t; o < nops; o += 128) {
        int row = o >> 2, c = o & 3;
        CP16(sdst + row * TROW + c * 16,
             g + (long long)(r0 + row) * ldg + k0 + c * 8);
    }
}

__global__ void __launch_bounds__(128) gemm_1t(
    const f16* __restrict__ Ah, int lda,
    const f16* __restrict__ Bh, int ldb,
    float* __restrict__ C, int ldc, int K)
{
    int rb = blockIdx.y, cb = blockIdx.x;
    int row0 = rb * 128, col0 = cb * 128;

    extern __shared__ char sm[];
    uint32_t sbase = smem_u32(sm);
    int t = threadIdx.x, w = t >> 5, l = t & 31;
    int wm = w & 1, wn = w >> 1;

    float acc[4][8][4];
#pragma unroll
    for (int i = 0; i < 4; i++)
#pragma unroll
        for (int j = 0; j < 8; j++)
#pragma unroll
            for (int q = 0; q < 4; q++) acc[i][j][q] = 0.f;

    int niter = K / 32;
    uint32_t stg[2] = {sbase, sbase + STAGE_B};

    tile_cp_n(Ah, lda, row0, 0, stg[0],        128, t);
    tile_cp_n(Bh, ldb, col0, 0, stg[0] + A_TB, 128, t);
    CP_COMMIT();

    int a_row = wm * 64 + (l & 15);
    int a_kb  = ((l >> 4) & 1) * 16;
    int b_row = wn * 64 + (l & 7) + ((l >> 4) & 1) * 8;
    int b_kb  = ((l >> 3) & 1) * 16;

    for (int it = 0; it < niter; it++) {
        if (it + 1 < niter) {
            uint32_t nb = stg[(it + 1) & 1];
            int k0 = (it + 1) * 32;
            tile_cp_n(Ah, lda, row0, k0, nb,        128, t);
            tile_cp_n(Bh, ldb, col0, k0, nb + A_TB, 128, t);
            CP_COMMIT();
            CP_WAIT1();
        } else {
            CP_WAIT0();
        }
        __syncthreads();

        uint32_t base = stg[it & 1];
#pragma unroll
        for (int ks = 0; ks < 2; ks++) {
            int kbyte = ks * 32;
            uint32_t ah[4][4], bh[8][2];
#pragma unroll
            for (int mf = 0; mf < 4; mf++) {
                uint32_t aaddr = base + (a_row + mf * 16) * TROW + kbyte + a_kb;
                ldsm_x4(ah[mf][0], ah[mf][1], ah[mf][2], ah[mf][3], aaddr);
            }
#pragma unroll
            for (int p = 0; p < 4; p++) {
                uint32_t baddr = base + A_TB + (b_row + p * 16) * TROW + kbyte + b_kb;
                uint32_t r0, r1, r2, r3;
                ldsm_x4(r0, r1, r2, r3, baddr);
                bh[2 * p][0] = r0;     bh[2 * p][1] = r1;
                bh[2 * p + 1][0] = r2; bh[2 * p + 1][1] = r3;
            }
#pragma unroll
            for (int mf = 0; mf < 4; mf++)
#pragma unroll
                for (int nf = 0; nf < 8; nf++) hmma(acc[mf][nf], ah[mf], bh[nf]);
        }
        __syncthreads();
    }

#pragma unroll
    for (int mf = 0; mf < 4; mf++) {
        int r_lo = row0 + wm * 64 + mf * 16 + (l >> 2);
#pragma unroll
        for (int nf = 0; nf < 8; nf++) {
            int cix = col0 + wn * 64 + nf * 8 + (l & 3) * 2;
            *(float2*)&C[(long long)r_lo * ldc + cix] =
                make_float2(acc[mf][nf][0], acc[mf][nf][1]);
            *(float2*)&C[(long long)(r_lo + 8) * ldc + cix] =
                make_float2(acc[mf][nf][2], acc[mf][nf][3]);
        }
    }
}

// ---------------------------------------------------------------------------
// Fused flash attention: QK 2-term (Q split), PV single-term (P fp16).
// One CTA = (head, PAIR of q-blocks {15-p, p}) -> exactly 34 KV-iters per CTA.
// 128 CTAs = one perfectly balanced wave.
// ---------------------------------------------------------------------------
#define FL_QROW 272
#define FL_VROW 144
#define FL_QT (128 * FL_QROW)          // 34816
#define FL_KT (64  * FL_QROW)          // 17408
#define FL_VT (128 * FL_VROW)          // 18432
#define FL_STG (FL_KT + FL_VT)         // 35840
#define FL_SMEM (2 * FL_QT + 2 * FL_STG)  // 141312

__device__ __forceinline__ void cp_rows(const f16* __restrict__ g, int ldg,
                                        int row0, int col0, uint32_t sdst,
                                        int stride, int cps_per_row, int nops, int t) {
    for (int o = t; o < nops; o += 256) {
        int r = o / cps_per_row, c = o % cps_per_row;
        CP16(sdst + r * stride + c * 16,
             g + (long long)(row0 + r) * ldg + col0 + c * 8);
    }
}

__global__ __launch_bounds__(256) void flash_k(
    const f16* __restrict__ qh, const f16* __restrict__ ql,
    const f16* __restrict__ kh, const f16* __restrict__ vth,
    f16* __restrict__ oh)
{
    int id = blockIdx.x;
    int h = id & 15;
    int pr = id >> 4;                  // 0..7
    int kvh = h >> 2;

    extern __shared__ char sm[];
    uint32_t S = smem_u32(sm);
    uint32_t smQ = S;
    int t = threadIdx.x, w = t >> 5, l = t & 31;
    int g = l >> 2, tg = l & 3;

    int a_row = w * 16 + (l & 15);
    int a_kb  = ((l >> 4) & 1) * 16;
    int b_sub = (l & 7) + ((l >> 4) & 1) * 8;
    int b_kb  = ((l >> 3) & 1) * 16;

    for (int qi = 0; qi < 2; qi++) {
        int qb = qi ? pr : 15 - pr;    // heavy block first
        int q0 = qb * 128;
        int niter = 2 * qb + 2;

        // all warps done with previous block's smem before reloading
        __syncthreads();

        cp_rows(qh, HID, q0, h * 128, smQ,         FL_QROW, 16, 2048, t);
        cp_rows(ql, HID, q0, h * 128, smQ + FL_QT, FL_QROW, 16, 2048, t);
        {
            uint32_t st = S + 2 * FL_QT;
            cp_rows(kh, 512, 0, kvh * 128, st,            FL_QROW, 16, 1024, t);
            cp_rows(vth, S_LEN, kvh * 128, 0, st + FL_KT, FL_VROW, 8, 1024, t);
        }
        CP_COMMIT();

        float acc[16][4];
#pragma unroll
        for (int nf = 0; nf < 16; nf++)
#pragma unroll
            for (int c = 0; c < 4; c++) acc[nf][c] = 0.f;
        float m0 = -1e30f, m1 = -1e30f, l0 = 0.f, l1 = 0.f;

        for (int jj = 0; jj < niter; jj++) {
            if (jj + 1 < niter) {
                uint32_t st = S + 2 * FL_QT + ((jj + 1) & 1) * FL_STG;
                int k0 = (jj + 1) * 64;
                cp_rows(kh, 512, k0, kvh * 128, st,            FL_QROW, 16, 1024, t);
                cp_rows(vth, S_LEN, kvh * 128, k0, st + FL_KT, FL_VROW, 8, 1024, t);
                CP_COMMIT();
                CP_WAIT1();
            } else {
                CP_WAIT0();
            }
            __syncthreads();

            bool active = !(jj == 2 * qb + 1 && w < 4);
            if (active) {
                uint32_t base = S + 2 * FL_QT + (jj & 1) * FL_STG;
                uint32_t bKh = base, bVh = base + FL_KT;

                float sf[8][4];
#pragma unroll
                for (int nf = 0; nf < 8; nf++)
#pragma unroll
                    for (int c = 0; c < 4; c++) sf[nf][c] = 0.f;

                // ---- S = Q K^T (2-term Q split) ----
#pragma unroll
                for (int ks = 0; ks < 8; ks++) {
                    uint32_t aaddr = smQ + a_row * FL_QROW + ks * 32 + a_kb;
                    uint32_t ah[4], al[4], bh[8][2];
                    ldsm_x4(ah[0], ah[1], ah[2], ah[3], aaddr);
                    ldsm_x4(al[0], al[1], al[2], al[3], aaddr + FL_QT);
#pragma unroll
                    for (int p = 0; p < 4; p++) {
                        uint32_t baddr = bKh + (p * 16 + b_sub) * FL_QROW + ks * 32 + b_kb;
                        uint32_t r0, r1, r2, r3;
                        ldsm_x4(r0, r1, r2, r3, baddr);
                        bh[2 * p][0] = r0;     bh[2 * p][1] = r1;
                        bh[2 * p + 1][0] = r2; bh[2 * p + 1][1] = r3;
                    }
#pragma unroll
                    for (int nf = 0; nf < 8; nf++) hmma(sf[nf], ah, bh[nf]);
#pragma unroll
                    for (int nf = 0; nf < 8; nf++) hmma(sf[nf], al, bh[nf]);
                }

                // ---- causal mask (diag blocks only) ----
                if (jj >= 2 * qb) {
                    int r0g = q0 + w * 16 + g;
#pragma unroll
                    for (int nf = 0; nf < 8; nf++) {
                        int cg = jj * 64 + nf * 8 + 2 * tg;
                        if (cg     > r0g)     sf[nf][0] = -1e30f;
                        if (cg + 1 > r0g)     sf[nf][1] = -1e30f;
                        if (cg     > r0g + 8) sf[nf][2] = -1e30f;
                        if (cg + 1 > r0g + 8) sf[nf][3] = -1e30f;
                    }
                }

                // ---- online softmax (base-2) ----
                float mx0 = m0, mx1 = m1;
#pragma unroll
                for (int nf = 0; nf < 8; nf++) {
                    mx0 = fmaxf(mx0, fmaxf(sf[nf][0], sf[nf][1]));
                    mx1 = fmaxf(mx1, fmaxf(sf[nf][2], sf[nf][3]));
                }
                mx0 = fmaxf(mx0, __shfl_xor_sync(0xffffffffu, mx0, 1));
                mx0 = fmaxf(mx0, __shfl_xor_sync(0xffffffffu, mx0, 2));
                mx1 = fmaxf(mx1, __shfl_xor_sync(0xffffffffu, mx1, 1));
                mx1 = fmaxf(mx1, __shfl_xor_sync(0xffffffffu, mx1, 2));
                float al0 = ex2(m0 - mx0), al1 = ex2(m1 - mx1);
                m0 = mx0; m1 = mx1;
                l0 *= al0; l1 *= al1;
#pragma unroll
                for (int nf = 0; nf < 8; nf++) {
                    float p0 = ex2(sf[nf][0] - m0);
                    float p1 = ex2(sf[nf][1] - m0);
                    float p2 = ex2(sf[nf][2] - m1);
                    float p3 = ex2(sf[nf][3] - m1);
                    sf[nf][0] = p0; sf[nf][1] = p1; sf[nf][2] = p2; sf[nf][3] = p3;
                    l0 += p0 + p1; l1 += p2 + p3;
                }
#pragma unroll
                for (int nf = 0; nf < 16; nf++) {
                    acc[nf][0] *= al0; acc[nf][1] *= al0;
                    acc[nf][2] *= al1; acc[nf][3] *= al1;
                }

                // ---- PV: acc += P V (single-term fp16 P) ----
#pragma unroll
                for (int u = 0; u < 4; u++) {
                    uint32_t pA_h[4];
#pragma unroll
                    for (int q = 0; q < 4; q++) {
                        float e0 = sf[2 * u + (q >> 1)][(q & 1) ? 2 : 0];
                        float e1 = sf[2 * u + (q >> 1)][(q & 1) ? 3 : 1];
                        pA_h[q] = pack_f16(e0, e1);
                    }
#pragma unroll
                    for (int p = 0; p < 8; p++) {
                        uint32_t vaddr = bVh + (p * 16 + b_sub) * FL_VROW + u * 32 + b_kb;
                        uint32_t r0, r1, r2, r3;
                        ldsm_x4(r0, r1, r2, r3, vaddr);
                        uint32_t vh0[2] = {r0, r1}, vh1[2] = {r2, r3};
                        hmma(acc[2 * p],     pA_h, vh0);
                        hmma(acc[2 * p + 1], pA_h, vh1);
                    }
                }
            }
            __syncthreads();
        }

        // ---- normalize + write fp16 attn ----
        l0 += __shfl_xor_sync(0xffffffffu, l0, 1);
        l0 += __shfl_xor_sync(0xffffffffu, l0, 2);
        l1 += __shfl_xor_sync(0xffffffffu, l1, 1);
        l1 += __shfl_xor_sync(0xffffffffu, l1, 2);
        float i0 = 1.f / l0, i1 = 1.f / l1;
        int row0 = q0 + w * 16 + g;
#pragma unroll
        for (int nf = 0; nf < 16; nf++) {
            int col = h * 128 + nf * 8 + 2 * tg;
            uint32_t hw0 = pack_f16(acc[nf][0] * i0, acc[nf][1] * i0);
            uint32_t hw1 = pack_f16(acc[nf][2] * i1, acc[nf][3] * i1);
            *(uint32_t*)&oh[(long long)row0 * HID + col]       = hw0;
            *(uint32_t*)&oh[(long long)(row0 + 8) * HID + col] = hw1;
        }
    }
}

// ---------------------------------------------------------------------------
__global__ __launch_bounds__(256) void conv1_k(const float* __restrict__ x,
                                               f16* __restrict__ h, int n)
{
    int i = blockIdx.x * 256 + threadIdx.x;
    if (i >= n) return;
    h[i] = __float2half_rn(x[i]);
}

// transpose + single fp16: dst[r][c] = src[c][scol0 + r]
__global__ __launch_bounds__(256) void transconv1_k(const float* __restrict__ src, int sld,
                                                    int scol0, f16* __restrict__ dh, int dld)
{
    __shared__ float tile[32][33];
    int tx = threadIdx.x, ty = threadIdx.y;
    int sr = blockIdx.x * 32;
    int sc = blockIdx.y * 32;
#pragma unroll
    for (int k = 0; k < 32; k += 8)
        tile[ty + k][tx] = src[(long long)(sr + ty + k) * sld + scol0 + sc + tx];
    __syncthreads();
#pragma unroll
    for (int k = 0; k < 32; k += 8) {
        long long o = (long long)(sc + ty + k) * dld + sr + tx;
        dh[o] = __float2half_rn(tile[tx][ty + k]);
    }
}

__global__ __launch_bounds__(256) void rope_split_k(const float* __restrict__ qkv,
    f16* __restrict__ qh, f16* __restrict__ ql, f16* __restrict__ kh)
{
    int idx = blockIdx.x * 256 + threadIdx.x;
    int i  = idx & 63;
    int hh = (idx >> 6) % 20;
    int s  = idx / (64 * 20);
    const float* p = qkv + (long long)s * QKV_N + ((hh < 16) ? hh * 128 : 2048 + (hh - 16) * 128);

    float f  = (float)s * __expf((float)i * -0.14391156831212787f);
    float sf = sinf(f), cf = cosf(f);     // full range reduction (f up to 2048)
    float x1 = p[i], x2 = p[i + 64];
    // outer trig args are in [-1,1]: fast approximations are accurate there
    float y1 = x1 * __cosf(sf) - x2 * __sinf(sf);
    float y2 = x2 * __cosf(cf) + x1 * __sinf(cf);

    if (hh < 16) {
        y1 *= QSCALE; y2 *= QSCALE;
        long long o = (long long)s * HID + hh * 128 + i;
        f16 a = __float2half_rn(y1);
        qh[o] = a; ql[o] = __float2half_rn(y1 - __half2float(a));
        f16 b = __float2half_rn(y2);
        qh[o + 64] = b; ql[o + 64] = __float2half_rn(y2 - __half2float(b));
    } else {
        long long o = (long long)s * 512 + (hh - 16) * 128 + i;
        kh[o]      = __float2half_rn(y1);
        kh[o + 64] = __float2half_rn(y2);
    }
}

// ---------------------------------------------------------------------------
extern "C" void kernel_launch(void* const* d_in, const int* in_sizes, int n_in,
                              void* d_out, int out_size)
{
    const float* hidden = (const float*)d_in[0];
    const float* W_attn = (const float*)d_in[3];
    const float* W_proj = (const float*)d_in[4];
    float* out = (float*)d_out;

    float* qkv;
    f16 *xh, *wh, *w2h, *qh, *ql, *kh, *vth;
    cudaGetSymbolAddress((void**)&qkv, g_qkv);
    cudaGetSymbolAddress((void**)&xh, g_xh);
    cudaGetSymbolAddress((void**)&wh, g_wh);   cudaGetSymbolAddress((void**)&w2h, g_w2h);
    cudaGetSymbolAddress((void**)&qh, g_qh);   cudaGetSymbolAddress((void**)&ql, g_ql);
    cudaGetSymbolAddress((void**)&kh, g_kh);   cudaGetSymbolAddress((void**)&vth, g_vth);

    cudaFuncSetAttribute(gemm_1t, cudaFuncAttributeMaxDynamicSharedMemorySize, GEMM_SMEM);
    cudaFuncSetAttribute(flash_k, cudaFuncAttributeMaxDynamicSharedMemorySize, FL_SMEM);

    // 1) converts
    conv1_k<<<(S_LEN * HID) / 256, 256>>>(hidden, xh, S_LEN * HID);
    transconv1_k<<<dim3(64, 96), dim3(32, 8)>>>(W_attn, QKV_N, 0, wh, HID);
    transconv1_k<<<dim3(64, 64), dim3(32, 8)>>>(W_proj, HID, 0, w2h, HID);

    // 2) qkv = hidden @ W_attn  (1-term fp16, fp32 accum)
    gemm_1t<<<dim3(QKV_N / 128, S_LEN / 128), 128, GEMM_SMEM>>>(
        xh, HID, wh, HID, qkv, QKV_N, HID);

    // 3) rope + split q, single k ; transpose v
    rope_split_k<<<(S_LEN * 20 * 64) / 256, 256>>>(qkv, qh, ql, kh);
    transconv1_k<<<dim3(64, 16), dim3(32, 8)>>>(qkv, QKV_N, 2560, vth, S_LEN);

    // 4) fused flash attention (paired q-blocks) -> fp16 attn (xh)
    flash_k<<<128, 256, FL_SMEM>>>(qh, ql, kh, vth, xh);

    // 5) out = attn @ W_proj  (1-term)
    gemm_1t<<<dim3(HID / 128, S_LEN / 128), 128, GEMM_SMEM>>>(
        xh, HID, w2h, HID, out, HID, HID);
}

// round 15
// speedup vs baseline: 1.0624x; 1.0624x over previous
#include <cuda_runtime.h>
#include <cuda_fp16.h>
#include <cstdint>

typedef __half f16;

#define S_LEN 2048
#define HID   2048
#define QKV_N 3072
#define NH    16
// q scale with log2(e) folded in (flash softmax runs in base-2)
#define QSCALE (0.08838834764831845f * 1.4426950408889634f)

// ---------------- scratch (static device allocations) ----------------
__device__ float g_qkv[S_LEN * QKV_N];
__device__ f16  g_xh[S_LEN * HID];                       // hidden fp16; reused for attn
__device__ f16  g_wh[QKV_N * HID];                       // W_attn^T (fp16)
__device__ f16  g_w2h[HID * HID];                        // W_proj^T (fp16)
__device__ f16  g_qh[S_LEN * HID];
__device__ f16  g_kh[S_LEN * 512];
__device__ f16  g_vth[512 * S_LEN];                      // V^T per kv head

// ---------------- helpers ----------------
__device__ __forceinline__ uint32_t smem_u32(const void* p) {
    uint32_t a;
    asm("{ .reg .u64 t; cvta.to.shared.u64 t, %1; cvt.u32.u64 %0, t; }" : "=r"(a) : "l"(p));
    return a;
}
#define CP16(dst, src) \
    asm volatile("cp.async.cg.shared.global [%0], [%1], 16;" :: "r"(dst), "l"(src))
#define CP_COMMIT() asm volatile("cp.async.commit_group;" ::: "memory")
#define CP_WAIT1()  asm volatile("cp.async.wait_group 1;" ::: "memory")
#define CP_WAIT0()  asm volatile("cp.async.wait_group 0;" ::: "memory")

__device__ __forceinline__ void ldsm_x4(uint32_t& r0, uint32_t& r1, uint32_t& r2,
                                        uint32_t& r3, uint32_t a) {
    asm volatile("ldmatrix.sync.aligned.m8n8.x4.shared.b16 {%0,%1,%2,%3}, [%4];"
                 : "=r"(r0), "=r"(r1), "=r"(r2), "=r"(r3) : "r"(a));
}
__device__ __forceinline__ void hmma(float* d, const uint32_t* a, const uint32_t* b) {
    asm volatile("mma.sync.aligned.m16n8k16.row.col.f32.f16.f16.f32 "
                 "{%0,%1,%2,%3}, {%4,%5,%6,%7}, {%8,%9}, {%0,%1,%2,%3};"
                 : "+f"(d[0]), "+f"(d[1]), "+f"(d[2]), "+f"(d[3])
                 : "r"(a[0]), "r"(a[1]), "r"(a[2]), "r"(a[3]), "r"(b[0]), "r"(b[1]));
}
__device__ __forceinline__ float ex2(float x) {
    float r; asm("ex2.approx.f32 %0, %1;" : "=f"(r) : "f"(x)); return r;
}
__device__ __forceinline__ uint32_t pack_f16(float lo, float hi) {
    __half2 h = __floats2half2_rn(lo, hi);
    return *reinterpret_cast<uint32_t*>(&h);
}

// ---------------------------------------------------------------------------
// single-term fp16 GEMM via mma.sync: C = A @ B^T, B is [N][K]
// 128 threads, 2x2 warp grid, warp tile 64x64, BM=128, BN=128, BK=32.
// ---------------------------------------------------------------------------
#define TROW    80
#define A_TB    (128 * TROW)           // 10240 B
#define B_TB    (128 * TROW)           // 10240 B
#define STAGE_B (A_TB + B_TB)          // 20480 B
#define GEMM_SMEM (2 * STAGE_B)        // 40960 B

__device__ __forceinline__ void tile_cp_n(const f16* __restrict__ g, int ldg,
                                          int r0, int k0, uint32_t sdst,
                                          int nrows, int t) {
    int nops = nrows * 4;
    for (int o = t; o < nops; o += 128) {
        int row = o >> 2, c = o & 3;
        CP16(sdst + row * TROW + c * 16,
             g + (long long)(r0 + row) * ldg + k0 + c * 8);
    }
}

__global__ void __launch_bounds__(128) gemm_1t(
    const f16* __restrict__ Ah, int lda,
    const f16* __restrict__ Bh, int ldb,
    float* __restrict__ C, int ldc, int K)
{
    int rb = blockIdx.y, cb = blockIdx.x;
    int row0 = rb * 128, col0 = cb * 128;

    extern __shared__ char sm[];
    uint32_t sbase = smem_u32(sm);
    int t = threadIdx.x, w = t >> 5, l = t & 31;
    int wm = w & 1, wn = w >> 1;

    float acc[4][8][4];
#pragma unroll
    for (int i = 0; i < 4; i++)
#pragma unroll
        for (int j = 0; j < 8; j++)
#pragma unroll
            for (int q = 0; q < 4; q++) acc[i][j][q] = 0.f;

    int niter = K / 32;
    uint32_t stg[2] = {sbase, sbase + STAGE_B};

    tile_cp_n(Ah, lda, row0, 0, stg[0],        128, t);
    tile_cp_n(Bh, ldb, col0, 0, stg[0] + A_TB, 128, t);
    CP_COMMIT();

    int a_row = wm * 64 + (l & 15);
    int a_kb  = ((l >> 4) & 1) * 16;
    int b_row = wn * 64 + (l & 7) + ((l >> 4) & 1) * 8;
    int b_kb  = ((l >> 3) & 1) * 16;

    for (int it = 0; it < niter; it++) {
        if (it + 1 < niter) {
            uint32_t nb = stg[(it + 1) & 1];
            int k0 = (it + 1) * 32;
            tile_cp_n(Ah, lda, row0, k0, nb,        128, t);
            tile_cp_n(Bh, ldb, col0, k0, nb + A_TB, 128, t);
            CP_COMMIT();
            CP_WAIT1();
        } else {
            CP_WAIT0();
        }
        __syncthreads();

        uint32_t base = stg[it & 1];
#pragma unroll
        for (int ks = 0; ks < 2; ks++) {
            int kbyte = ks * 32;
            uint32_t ah[4][4], bh[8][2];
#pragma unroll
            for (int mf = 0; mf < 4; mf++) {
                uint32_t aaddr = base + (a_row + mf * 16) * TROW + kbyte + a_kb;
                ldsm_x4(ah[mf][0], ah[mf][1], ah[mf][2], ah[mf][3], aaddr);
            }
#pragma unroll
            for (int p = 0; p < 4; p++) {
                uint32_t baddr = base + A_TB + (b_row + p * 16) * TROW + kbyte + b_kb;
                uint32_t r0, r1, r2, r3;
                ldsm_x4(r0, r1, r2, r3, baddr);
                bh[2 * p][0] = r0;     bh[2 * p][1] = r1;
                bh[2 * p + 1][0] = r2; bh[2 * p + 1][1] = r3;
            }
#pragma unroll
            for (int mf = 0; mf < 4; mf++)
#pragma unroll
                for (int nf = 0; nf < 8; nf++) hmma(acc[mf][nf], ah[mf], bh[nf]);
        }
        __syncthreads();
    }

#pragma unroll
    for (int mf = 0; mf < 4; mf++) {
        int r_lo = row0 + wm * 64 + mf * 16 + (l >> 2);
#pragma unroll
        for (int nf = 0; nf < 8; nf++) {
            int cix = col0 + wn * 64 + nf * 8 + (l & 3) * 2;
            *(float2*)&C[(long long)r_lo * ldc + cix] =
                make_float2(acc[mf][nf][0], acc[mf][nf][1]);
            *(float2*)&C[(long long)(r_lo + 8) * ldc + cix] =
                make_float2(acc[mf][nf][2], acc[mf][nf][3]);
        }
    }
}

// ---------------------------------------------------------------------------
// Fused flash attention: single-term fp16 QK and PV, fp32 accum.
// One CTA = (head, 128-row q block), heavy-first; 106 KB smem -> 2 CTAs/SM.
// ---------------------------------------------------------------------------
#define FL_QROW 272
#define FL_VROW 144
#define FL_QT (128 * FL_QROW)          // 34816
#define FL_KT (64  * FL_QROW)          // 17408
#define FL_VT (128 * FL_VROW)          // 18432
#define FL_STG (FL_KT + FL_VT)         // 35840
#define FL_SMEM (FL_QT + 2 * FL_STG)   // 106496 -> 2 CTAs/SM

__device__ __forceinline__ void cp_rows(const f16* __restrict__ g, int ldg,
                                        int row0, int col0, uint32_t sdst,
                                        int stride, int cps_per_row, int nops, int t) {
    for (int o = t; o < nops; o += 256) {
        int r = o / cps_per_row, c = o % cps_per_row;
        CP16(sdst + r * stride + c * 16,
             g + (long long)(row0 + r) * ldg + col0 + c * 8);
    }
}

__global__ __launch_bounds__(256) void flash_k(
    const f16* __restrict__ qh,
    const f16* __restrict__ kh, const f16* __restrict__ vth,
    f16* __restrict__ oh)
{
    int id = blockIdx.x;
    int qb = 15 - (id >> 4);           // heavy q-blocks first
    int h = id & 15;
    int kvh = h >> 2;
    int q0 = qb * 128;

    extern __shared__ char sm[];
    uint32_t S = smem_u32(sm);
    uint32_t smQ = S;
    uint32_t kvS = S + FL_QT;
    int t = threadIdx.x, w = t >> 5, l = t & 31;
    int g = l >> 2, tg = l & 3;

    cp_rows(qh, HID, q0, h * 128, smQ, FL_QROW, 16, 2048, t);
    cp_rows(kh, 512, 0, kvh * 128, kvS,            FL_QROW, 16, 1024, t);
    cp_rows(vth, S_LEN, kvh * 128, 0, kvS + FL_KT, FL_VROW, 8, 1024, t);
    CP_COMMIT();

    float acc[16][4];
#pragma unroll
    for (int nf = 0; nf < 16; nf++)
#pragma unroll
        for (int c = 0; c < 4; c++) acc[nf][c] = 0.f;
    float m0 = -1e30f, m1 = -1e30f, l0 = 0.f, l1 = 0.f;

    int niter = 2 * qb + 2;

    int a_row = w * 16 + (l & 15);
    int a_kb  = ((l >> 4) & 1) * 16;
    int b_sub = (l & 7) + ((l >> 4) & 1) * 8;
    int b_kb  = ((l >> 3) & 1) * 16;

    for (int jj = 0; jj < niter; jj++) {
        if (jj + 1 < niter) {
            uint32_t st = kvS + ((jj + 1) & 1) * FL_STG;
            int k0 = (jj + 1) * 64;
            cp_rows(kh, 512, k0, kvh * 128, st,            FL_QROW, 16, 1024, t);
            cp_rows(vth, S_LEN, kvh * 128, k0, st + FL_KT, FL_VROW, 8, 1024, t);
            CP_COMMIT();
            CP_WAIT1();
        } else {
            CP_WAIT0();
        }
        __syncthreads();

        bool active = !(jj == 2 * qb + 1 && w < 4);
        if (active) {
            uint32_t base = kvS + (jj & 1) * FL_STG;
            uint32_t bKh = base, bVh = base + FL_KT;

            float sf[8][4];
#pragma unroll
            for (int nf = 0; nf < 8; nf++)
#pragma unroll
                for (int c = 0; c < 4; c++) sf[nf][c] = 0.f;

            // ---- S = Q K^T (single-term fp16) ----
#pragma unroll
            for (int ks = 0; ks < 8; ks++) {
                uint32_t aaddr = smQ + a_row * FL_QROW + ks * 32 + a_kb;
                uint32_t ah[4], bh[8][2];
                ldsm_x4(ah[0], ah[1], ah[2], ah[3], aaddr);
#pragma unroll
                for (int p = 0; p < 4; p++) {
                    uint32_t baddr = bKh + (p * 16 + b_sub) * FL_QROW + ks * 32 + b_kb;
                    uint32_t r0, r1, r2, r3;
                    ldsm_x4(r0, r1, r2, r3, baddr);
                    bh[2 * p][0] = r0;     bh[2 * p][1] = r1;
                    bh[2 * p + 1][0] = r2; bh[2 * p + 1][1] = r3;
                }
#pragma unroll
                for (int nf = 0; nf < 8; nf++) hmma(sf[nf], ah, bh[nf]);
            }

            // ---- causal mask (diag blocks only) ----
            if (jj >= 2 * qb) {
                int r0g = q0 + w * 16 + g;
#pragma unroll
                for (int nf = 0; nf < 8; nf++) {
                    int cg = jj * 64 + nf * 8 + 2 * tg;
                    if (cg     > r0g)     sf[nf][0] = -1e30f;
                    if (cg + 1 > r0g)     sf[nf][1] = -1e30f;
                    if (cg     > r0g + 8) sf[nf][2] = -1e30f;
                    if (cg + 1 > r0g + 8) sf[nf][3] = -1e30f;
                }
            }

            // ---- online softmax (base-2) ----
            float mx0 = m0, mx1 = m1;
#pragma unroll
            for (int nf = 0; nf < 8; nf++) {
                mx0 = fmaxf(mx0, fmaxf(sf[nf][0], sf[nf][1]));
                mx1 = fmaxf(mx1, fmaxf(sf[nf][2], sf[nf][3]));
            }
            mx0 = fmaxf(mx0, __shfl_xor_sync(0xffffffffu, mx0, 1));
            mx0 = fmaxf(mx0, __shfl_xor_sync(0xffffffffu, mx0, 2));
            mx1 = fmaxf(mx1, __shfl_xor_sync(0xffffffffu, mx1, 1));
            mx1 = fmaxf(mx1, __shfl_xor_sync(0xffffffffu, mx1, 2));
            float al0 = ex2(m0 - mx0), al1 = ex2(m1 - mx1);
            m0 = mx0; m1 = mx1;
            l0 *= al0; l1 *= al1;
#pragma unroll
            for (int nf = 0; nf < 8; nf++) {
                float p0 = ex2(sf[nf][0] - m0);
                float p1 = ex2(sf[nf][1] - m0);
                float p2 = ex2(sf[nf][2] - m1);
                float p3 = ex2(sf[nf][3] - m1);
                sf[nf][0] = p0; sf[nf][1] = p1; sf[nf][2] = p2; sf[nf][3] = p3;
                l0 += p0 + p1; l1 += p2 + p3;
            }
#pragma unroll
            for (int nf = 0; nf < 16; nf++) {
                acc[nf][0] *= al0; acc[nf][1] *= al0;
                acc[nf][2] *= al1; acc[nf][3] *= al1;
            }

            // ---- PV: acc += P V (single-term fp16 P) ----
#pragma unroll
            for (int u = 0; u < 4; u++) {
                uint32_t pA_h[4];
#pragma unroll
                for (int q = 0; q < 4; q++) {
                    float e0 = sf[2 * u + (q >> 1)][(q & 1) ? 2 : 0];
                    float e1 = sf[2 * u + (q >> 1)][(q & 1) ? 3 : 1];
                    pA_h[q] = pack_f16(e0, e1);
                }
#pragma unroll
                for (int p = 0; p < 8; p++) {
                    uint32_t vaddr = bVh + (p * 16 + b_sub) * FL_VROW + u * 32 + b_kb;
                    uint32_t r0, r1, r2, r3;
                    ldsm_x4(r0, r1, r2, r3, vaddr);
                    uint32_t vh0[2] = {r0, r1}, vh1[2] = {r2, r3};
                    hmma(acc[2 * p],     pA_h, vh0);
                    hmma(acc[2 * p + 1], pA_h, vh1);
                }
            }
        }
        __syncthreads();
    }

    l0 += __shfl_xor_sync(0xffffffffu, l0, 1);
    l0 += __shfl_xor_sync(0xffffffffu, l0, 2);
    l1 += __shfl_xor_sync(0xffffffffu, l1, 1);
    l1 += __shfl_xor_sync(0xffffffffu, l1, 2);
    float i0 = 1.f / l0, i1 = 1.f / l1;
    int row0 = q0 + w * 16 + g;
#pragma unroll
    for (int nf = 0; nf < 16; nf++) {
        int col = h * 128 + nf * 8 + 2 * tg;
        uint32_t hw0 = pack_f16(acc[nf][0] * i0, acc[nf][1] * i0);
        uint32_t hw1 = pack_f16(acc[nf][2] * i1, acc[nf][3] * i1);
        *(uint32_t*)&oh[(long long)row0 * HID + col]       = hw0;
        *(uint32_t*)&oh[(long long)(row0 + 8) * HID + col] = hw1;
    }
}

// ---------------------------------------------------------------------------
__global__ __launch_bounds__(256) void conv1_k(const float* __restrict__ x,
                                               f16* __restrict__ h, int n)
{
    int i = blockIdx.x * 256 + threadIdx.x;
    if (i >= n) return;
    h[i] = __float2half_rn(x[i]);
}

// transpose + single fp16: dst[r][c] = src[c][scol0 + r]
__global__ __launch_bounds__(256) void transconv1_k(const float* __restrict__ src, int sld,
                                                    int scol0, f16* __restrict__ dh, int dld)
{
    __shared__ float tile[32][33];
    int tx = threadIdx.x, ty = threadIdx.y;
    int sr = blockIdx.x * 32;
    int sc = blockIdx.y * 32;
#pragma unroll
    for (int k = 0; k < 32; k += 8)
        tile[ty + k][tx] = src[(long long)(sr + ty + k) * sld + scol0 + sc + tx];
    __syncthreads();
#pragma unroll
    for (int k = 0; k < 32; k += 8) {
        long long o = (long long)(sc + ty + k) * dld + sr + tx;
        dh[o] = __float2half_rn(tile[tx][ty + k]);
    }
}

__global__ __launch_bounds__(256) void rope_split_k(const float* __restrict__ qkv,
    f16* __restrict__ qh, f16* __restrict__ kh)
{
    int idx = blockIdx.x * 256 + threadIdx.x;
    int i  = idx & 63;
    int hh = (idx >> 6) % 20;
    int s  = idx / (64 * 20);
    const float* p = qkv + (long long)s * QKV_N + ((hh < 16) ? hh * 128 : 2048 + (hh - 16) * 128);

    float f  = (float)s * __expf((float)i * -0.14391156831212787f);
    float sf = sinf(f), cf = cosf(f);     // full range reduction (f up to 2048)
    float x1 = p[i], x2 = p[i + 64];
    // outer trig args are in [-1,1]: fast approximations are accurate there
    float y1 = x1 * __cosf(sf) - x2 * __sinf(sf);
    float y2 = x2 * __cosf(cf) + x1 * __sinf(cf);

    if (hh < 16) {
        y1 *= QSCALE; y2 *= QSCALE;
        long long o = (long long)s * HID + hh * 128 + i;
        qh[o]      = __float2half_rn(y1);
        qh[o + 64] = __float2half_rn(y2);
    } else {
        long long o = (long long)s * 512 + (hh - 16) * 128 + i;
        kh[o]      = __float2half_rn(y1);
        kh[o + 64] = __float2half_rn(y2);
    }
}

// ---------------------------------------------------------------------------
extern "C" void kernel_launch(void* const* d_in, const int* in_sizes, int n_in,
                              void* d_out, int out_size)
{
    const float* hidden = (const float*)d_in[0];
    const float* W_attn = (const float*)d_in[3];
    const float* W_proj = (const float*)d_in[4];
    float* out = (float*)d_out;

    float* qkv;
    f16 *xh, *wh, *w2h, *qh, *kh, *vth;
    cudaGetSymbolAddress((void**)&qkv, g_qkv);
    cudaGetSymbolAddress((void**)&xh, g_xh);
    cudaGetSymbolAddress((void**)&wh, g_wh);   cudaGetSymbolAddress((void**)&w2h, g_w2h);
    cudaGetSymbolAddress((void**)&qh, g_qh);
    cudaGetSymbolAddress((void**)&kh, g_kh);   cudaGetSymbolAddress((void**)&vth, g_vth);

    cudaFuncSetAttribute(gemm_1t, cudaFuncAttributeMaxDynamicSharedMemorySize, GEMM_SMEM);
    cudaFuncSetAttribute(flash_k, cudaFuncAttributeMaxDynamicSharedMemorySize, FL_SMEM);

    // 1) converts
    conv1_k<<<(S_LEN * HID) / 256, 256>>>(hidden, xh, S_LEN * HID);
    transconv1_k<<<dim3(64, 96), dim3(32, 8)>>>(W_attn, QKV_N, 0, wh, HID);
    transconv1_k<<<dim3(64, 64), dim3(32, 8)>>>(W_proj, HID, 0, w2h, HID);

    // 2) qkv = hidden @ W_attn  (1-term fp16, fp32 accum)
    gemm_1t<<<dim3(QKV_N / 128, S_LEN / 128), 128, GEMM_SMEM>>>(
        xh, HID, wh, HID, qkv, QKV_N, HID);

    // 3) rope (fp16 q and k) ; transpose v
    rope_split_k<<<(S_LEN * 20 * 64) / 256, 256>>>(qkv, qh, kh);
    transconv1_k<<<dim3(64, 16), dim3(32, 8)>>>(qkv, QKV_N, 2560, vth, S_LEN);

    // 4) fused flash attention (heavy-first, 2 CTAs/SM) -> fp16 attn (xh)
    flash_k<<<256, 256, FL_SMEM>>>(qh, kh, vth, xh);

    // 5) out = attn @ W_proj  (1-term)
    gemm_1t<<<dim3(HID / 128, S_LEN / 128), 128, GEMM_SMEM>>>(
        xh, HID, w2h, HID, out, HID, HID);
}

// round 16
// speedup vs baseline: 1.0711x; 1.0082x over previous
#include <cuda_runtime.h>
#include <cuda_fp16.h>
#include <cstdint>

typedef __half f16;

#define S_LEN 2048
#define HID   2048
#define QKV_N 3072
#define NH    16
// q scale with log2(e) folded in (flash softmax runs in base-2)
#define QSCALE (0.08838834764831845f * 1.4426950408889634f)

// ---------------- scratch (static device allocations) ----------------
__device__ f16  g_qkvh[S_LEN * QKV_N];                   // fp16 qkv intermediate
__device__ f16  g_xh[S_LEN * HID];                       // hidden fp16; reused for attn
__device__ f16  g_wh[QKV_N * HID];                       // W_attn^T (fp16)
__device__ f16  g_w2h[HID * HID];                        // W_proj^T (fp16)
__device__ f16  g_qh[S_LEN * HID];
__device__ f16  g_kh[S_LEN * 512];
__device__ f16  g_vth[512 * S_LEN];                      // V^T per kv head

// ---------------- helpers ----------------
__device__ __forceinline__ uint32_t smem_u32(const void* p) {
    uint32_t a;
    asm("{ .reg .u64 t; cvta.to.shared.u64 t, %1; cvt.u32.u64 %0, t; }" : "=r"(a) : "l"(p));
    return a;
}
#define CP16(dst, src) \
    asm volatile("cp.async.cg.shared.global [%0], [%1], 16;" :: "r"(dst), "l"(src))
#define CP_COMMIT() asm volatile("cp.async.commit_group;" ::: "memory")
#define CP_WAIT1()  asm volatile("cp.async.wait_group 1;" ::: "memory")
#define CP_WAIT0()  asm volatile("cp.async.wait_group 0;" ::: "memory")

__device__ __forceinline__ void ldsm_x4(uint32_t& r0, uint32_t& r1, uint32_t& r2,
                                        uint32_t& r3, uint32_t a) {
    asm volatile("ldmatrix.sync.aligned.m8n8.x4.shared.b16 {%0,%1,%2,%3}, [%4];"
                 : "=r"(r0), "=r"(r1), "=r"(r2), "=r"(r3) : "r"(a));
}
__device__ __forceinline__ void hmma(float* d, const uint32_t* a, const uint32_t* b) {
    asm volatile("mma.sync.aligned.m16n8k16.row.col.f32.f16.f16.f32 "
                 "{%0,%1,%2,%3}, {%4,%5,%6,%7}, {%8,%9}, {%0,%1,%2,%3};"
                 : "+f"(d[0]), "+f"(d[1]), "+f"(d[2]), "+f"(d[3])
                 : "r"(a[0]), "r"(a[1]), "r"(a[2]), "r"(a[3]), "r"(b[0]), "r"(b[1]));
}
__device__ __forceinline__ float ex2(float x) {
    float r; asm("ex2.approx.f32 %0, %1;" : "=f"(r) : "f"(x)); return r;
}
__device__ __forceinline__ uint32_t pack_f16(float lo, float hi) {
    __half2 h = __floats2half2_rn(lo, hi);
    return *reinterpret_cast<uint32_t*>(&h);
}

// ---------------------------------------------------------------------------
// single-term fp16 GEMM via mma.sync: C = A @ B^T, B is [N][K]
// 128 threads, 2x2 warp grid, warp tile 64x64, BM=128, BN=128, BK=32.
// Writes fp32 C, or fp16 Ch when Ch != nullptr.
// ---------------------------------------------------------------------------
#define TROW    80
#define A_TB    (128 * TROW)           // 10240 B
#define B_TB    (128 * TROW)           // 10240 B
#define STAGE_B (A_TB + B_TB)          // 20480 B
#define GEMM_SMEM (2 * STAGE_B)        // 40960 B

__device__ __forceinline__ void tile_cp_n(const f16* __restrict__ g, int ldg,
                                          int r0, int k0, uint32_t sdst,
                                          int nrows, int t) {
    int nops = nrows * 4;
    for (int o = t; o < nops; o += 128) {
        int row = o >> 2, c = o & 3;
        CP16(sdst + row * TROW + c * 16,
             g + (long long)(r0 + row) * ldg + k0 + c * 8);
    }
}

__global__ void __launch_bounds__(128) gemm_1t(
    const f16* __restrict__ Ah, int lda,
    const f16* __restrict__ Bh, int ldb,
    float* __restrict__ C, f16* __restrict__ Ch, int ldc, int K)
{
    int rb = blockIdx.y, cb = blockIdx.x;
    int row0 = rb * 128, col0 = cb * 128;

    extern __shared__ char sm[];
    uint32_t sbase = smem_u32(sm);
    int t = threadIdx.x, w = t >> 5, l = t & 31;
    int wm = w & 1, wn = w >> 1;

    float acc[4][8][4];
#pragma unroll
    for (int i = 0; i < 4; i++)
#pragma unroll
        for (int j = 0; j < 8; j++)
#pragma unroll
            for (int q = 0; q < 4; q++) acc[i][j][q] = 0.f;

    int niter = K / 32;
    uint32_t stg[2] = {sbase, sbase + STAGE_B};

    tile_cp_n(Ah, lda, row0, 0, stg[0],        128, t);
    tile_cp_n(Bh, ldb, col0, 0, stg[0] + A_TB, 128, t);
    CP_COMMIT();

    int a_row = wm * 64 + (l & 15);
    int a_kb  = ((l >> 4) & 1) * 16;
    int b_row = wn * 64 + (l & 7) + ((l >> 4) & 1) * 8;
    int b_kb  = ((l >> 3) & 1) * 16;

    for (int it = 0; it < niter; it++) {
        if (it + 1 < niter) {
            uint32_t nb = stg[(it + 1) & 1];
            int k0 = (it + 1) * 32;
            tile_cp_n(Ah, lda, row0, k0, nb,        128, t);
            tile_cp_n(Bh, ldb, col0, k0, nb + A_TB, 128, t);
            CP_COMMIT();
            CP_WAIT1();
        } else {
            CP_WAIT0();
        }
        __syncthreads();

        uint32_t base = stg[it & 1];
#pragma unroll
        for (int ks = 0; ks < 2; ks++) {
            int kbyte = ks * 32;
            uint32_t ah[4][4], bh[8][2];
#pragma unroll
            for (int mf = 0; mf < 4; mf++) {
                uint32_t aaddr = base + (a_row + mf * 16) * TROW + kbyte + a_kb;
                ldsm_x4(ah[mf][0], ah[mf][1], ah[mf][2], ah[mf][3], aaddr);
            }
#pragma unroll
            for (int p = 0; p < 4; p++) {
                uint32_t baddr = base + A_TB + (b_row + p * 16) * TROW + kbyte + b_kb;
                uint32_t r0, r1, r2, r3;
                ldsm_x4(r0, r1, r2, r3, baddr);
                bh[2 * p][0] = r0;     bh[2 * p][1] = r1;
                bh[2 * p + 1][0] = r2; bh[2 * p + 1][1] = r3;
            }
#pragma unroll
            for (int mf = 0; mf < 4; mf++)
#pragma unroll
                for (int nf = 0; nf < 8; nf++) hmma(acc[mf][nf], ah[mf], bh[nf]);
        }
        __syncthreads();
    }

    if (Ch) {
#pragma unroll
        for (int mf = 0; mf < 4; mf++) {
            int r_lo = row0 + wm * 64 + mf * 16 + (l >> 2);
#pragma unroll
            for (int nf = 0; nf < 8; nf++) {
                int cix = col0 + wn * 64 + nf * 8 + (l & 3) * 2;
                *(uint32_t*)&Ch[(long long)r_lo * ldc + cix] =
                    pack_f16(acc[mf][nf][0], acc[mf][nf][1]);
                *(uint32_t*)&Ch[(long long)(r_lo + 8) * ldc + cix] =
                    pack_f16(acc[mf][nf][2], acc[mf][nf][3]);
            }
        }
    } else {
#pragma unroll
        for (int mf = 0; mf < 4; mf++) {
            int r_lo = row0 + wm * 64 + mf * 16 + (l >> 2);
#pragma unroll
            for (int nf = 0; nf < 8; nf++) {
                int cix = col0 + wn * 64 + nf * 8 + (l & 3) * 2;
                *(float2*)&C[(long long)r_lo * ldc + cix] =
                    make_float2(acc[mf][nf][0], acc[mf][nf][1]);
                *(float2*)&C[(long long)(r_lo + 8) * ldc + cix] =
                    make_float2(acc[mf][nf][2], acc[mf][nf][3]);
            }
        }
    }
}

// ---------------------------------------------------------------------------
// Fused flash attention: single-term fp16 QK/PV, fp32 accum.
// Q fragments hoisted into registers (loaded once, KV loop does B-ldsm only).
// ---------------------------------------------------------------------------
#define FL_QROW 272
#define FL_VROW 144
#define FL_QT (128 * FL_QROW)          // 34816
#define FL_KT (64  * FL_QROW)          // 17408
#define FL_VT (128 * FL_VROW)          // 18432
#define FL_STG (FL_KT + FL_VT)         // 35840
#define FL_SMEM (FL_QT + 2 * FL_STG)   // 106496

__device__ __forceinline__ void cp_rows(const f16* __restrict__ g, int ldg,
                                        int row0, int col0, uint32_t sdst,
                                        int stride, int cps_per_row, int nops, int t) {
    for (int o = t; o < nops; o += 256) {
        int r = o / cps_per_row, c = o % cps_per_row;
        CP16(sdst + r * stride + c * 16,
             g + (long long)(row0 + r) * ldg + col0 + c * 8);
    }
}

__global__ __launch_bounds__(256) void flash_k(
    const f16* __restrict__ qh,
    const f16* __restrict__ kh, const f16* __restrict__ vth,
    f16* __restrict__ oh)
{
    int id = blockIdx.x;
    int qb = 15 - (id >> 4);           // heavy q-blocks first
    int h = id & 15;
    int kvh = h >> 2;
    int q0 = qb * 128;

    extern __shared__ char sm[];
    uint32_t S = smem_u32(sm);
    uint32_t smQ = S;
    uint32_t kvS = S + FL_QT;
    int t = threadIdx.x, w = t >> 5, l = t & 31;
    int g = l >> 2, tg = l & 3;

    cp_rows(qh, HID, q0, h * 128, smQ, FL_QROW, 16, 2048, t);
    cp_rows(kh, 512, 0, kvh * 128, kvS,            FL_QROW, 16, 1024, t);
    cp_rows(vth, S_LEN, kvh * 128, 0, kvS + FL_KT, FL_VROW, 8, 1024, t);
    CP_COMMIT();

    float acc[16][4];
#pragma unroll
    for (int nf = 0; nf < 16; nf++)
#pragma unroll
        for (int c = 0; c < 4; c++) acc[nf][c] = 0.f;
    float m0 = -1e30f, m1 = -1e30f, l0 = 0.f, l1 = 0.f;

    int niter = 2 * qb + 2;

    int a_row = w * 16 + (l & 15);
    int a_kb  = ((l >> 4) & 1) * 16;
    int b_sub = (l & 7) + ((l >> 4) & 1) * 8;
    int b_kb  = ((l >> 3) & 1) * 16;

    uint32_t ahq[8][4];                // hoisted Q fragments (loaded at jj==0)

    for (int jj = 0; jj < niter; jj++) {
        if (jj + 1 < niter) {
            uint32_t st = kvS + ((jj + 1) & 1) * FL_STG;
            int k0 = (jj + 1) * 64;
            cp_rows(kh, 512, k0, kvh * 128, st,            FL_QROW, 16, 1024, t);
            cp_rows(vth, S_LEN, kvh * 128, k0, st + FL_KT, FL_VROW, 8, 1024, t);
            CP_COMMIT();
            CP_WAIT1();
        } else {
            CP_WAIT0();
        }
        __syncthreads();

        if (jj == 0) {
#pragma unroll
            for (int ks = 0; ks < 8; ks++) {
                uint32_t aaddr = smQ + a_row * FL_QROW + ks * 32 + a_kb;
                ldsm_x4(ahq[ks][0], ahq[ks][1], ahq[ks][2], ahq[ks][3], aaddr);
            }
        }

        bool active = !(jj == 2 * qb + 1 && w < 4);
        if (active) {
            uint32_t base = kvS + (jj & 1) * FL_STG;
            uint32_t bKh = base, bVh = base + FL_KT;

            float sf[8][4];
#pragma unroll
            for (int nf = 0; nf < 8; nf++)
#pragma unroll
                for (int c = 0; c < 4; c++) sf[nf][c] = 0.f;

            // ---- S = Q K^T (Q frags in registers, B-ldsm only) ----
#pragma unroll
            for (int ks = 0; ks < 8; ks++) {
                uint32_t bh[8][2];
#pragma unroll
                for (int p = 0; p < 4; p++) {
                    uint32_t baddr = bKh + (p * 16 + b_sub) * FL_QROW + ks * 32 + b_kb;
                    uint32_t r0, r1, r2, r3;
                    ldsm_x4(r0, r1, r2, r3, baddr);
                    bh[2 * p][0] = r0;     bh[2 * p][1] = r1;
                    bh[2 * p + 1][0] = r2; bh[2 * p + 1][1] = r3;
                }
#pragma unroll
                for (int nf = 0; nf < 8; nf++) hmma(sf[nf], ahq[ks], bh[nf]);
            }

            // ---- causal mask (diag blocks only) ----
            if (jj >= 2 * qb) {
                int r0g = q0 + w * 16 + g;
#pragma unroll
                for (int nf = 0; nf < 8; nf++) {
                    int cg = jj * 64 + nf * 8 + 2 * tg;
                    if (cg     > r0g)     sf[nf][0] = -1e30f;
                    if (cg + 1 > r0g)     sf[nf][1] = -1e30f;
                    if (cg     > r0g + 8) sf[nf][2] = -1e30f;
                    if (cg + 1 > r0g + 8) sf[nf][3] = -1e30f;
                }
            }

            // ---- online softmax (base-2) ----
            float mx0 = m0, mx1 = m1;
#pragma unroll
            for (int nf = 0; nf < 8; nf++) {
                mx0 = fmaxf(mx0, fmaxf(sf[nf][0], sf[nf][1]));
                mx1 = fmaxf(mx1, fmaxf(sf[nf][2], sf[nf][3]));
            }
            mx0 = fmaxf(mx0, __shfl_xor_sync(0xffffffffu, mx0, 1));
            mx0 = fmaxf(mx0, __shfl_xor_sync(0xffffffffu, mx0, 2));
            mx1 = fmaxf(mx1, __shfl_xor_sync(0xffffffffu, mx1, 1));
            mx1 = fmaxf(mx1, __shfl_xor_sync(0xffffffffu, mx1, 2));
            float al0 = ex2(m0 - mx0), al1 = ex2(m1 - mx1);
            m0 = mx0; m1 = mx1;
            l0 *= al0; l1 *= al1;
#pragma unroll
            for (int nf = 0; nf < 8; nf++) {
                float p0 = ex2(sf[nf][0] - m0);
                float p1 = ex2(sf[nf][1] - m0);
                float p2 = ex2(sf[nf][2] - m1);
                float p3 = ex2(sf[nf][3] - m1);
                sf[nf][0] = p0; sf[nf][1] = p1; sf[nf][2] = p2; sf[nf][3] = p3;
                l0 += p0 + p1; l1 += p2 + p3;
            }
#pragma unroll
            for (int nf = 0; nf < 16; nf++) {
                acc[nf][0] *= al0; acc[nf][1] *= al0;
                acc[nf][2] *= al1; acc[nf][3] *= al1;
            }

            // ---- PV: acc += P V (single-term fp16 P) ----
#pragma unroll
            for (int u = 0; u < 4; u++) {
                uint32_t pA_h[4];
#pragma unroll
                for (int q = 0; q < 4; q++) {
                    float e0 = sf[2 * u + (q >> 1)][(q & 1) ? 2 : 0];
                    float e1 = sf[2 * u + (q >> 1)][(q & 1) ? 3 : 1];
                    pA_h[q] = pack_f16(e0, e1);
                }
#pragma unroll
                for (int p = 0; p < 8; p++) {
                    uint32_t vaddr = bVh + (p * 16 + b_sub) * FL_VROW + u * 32 + b_kb;
                    uint32_t r0, r1, r2, r3;
                    ldsm_x4(r0, r1, r2, r3, vaddr);
                    uint32_t vh0[2] = {r0, r1}, vh1[2] = {r2, r3};
                    hmma(acc[2 * p],     pA_h, vh0);
                    hmma(acc[2 * p + 1], pA_h, vh1);
                }
            }
        }
        __syncthreads();
    }

    l0 += __shfl_xor_sync(0xffffffffu, l0, 1);
    l0 += __shfl_xor_sync(0xffffffffu, l0, 2);
    l1 += __shfl_xor_sync(0xffffffffu, l1, 1);
    l1 += __shfl_xor_sync(0xffffffffu, l1, 2);
    float i0 = 1.f / l0, i1 = 1.f / l1;
    int row0 = q0 + w * 16 + g;
#pragma unroll
    for (int nf = 0; nf < 16; nf++) {
        int col = h * 128 + nf * 8 + 2 * tg;
        uint32_t hw0 = pack_f16(acc[nf][0] * i0, acc[nf][1] * i0);
        uint32_t hw1 = pack_f16(acc[nf][2] * i1, acc[nf][3] * i1);
        *(uint32_t*)&oh[(long long)row0 * HID + col]       = hw0;
        *(uint32_t*)&oh[(long long)(row0 + 8) * HID + col] = hw1;
    }
}

// ---------------------------------------------------------------------------
__global__ __launch_bounds__(256) void conv1_k(const float* __restrict__ x,
                                               f16* __restrict__ h, int n)
{
    int i = blockIdx.x * 256 + threadIdx.x;
    if (i >= n) return;
    h[i] = __float2half_rn(x[i]);
}

// transpose + convert fp32->fp16 (weights): dst[r][c] = src[c][scol0 + r]
__global__ __launch_bounds__(256) void transconv1_k(const float* __restrict__ src, int sld,
                                                    int scol0, f16* __restrict__ dh, int dld)
{
    __shared__ float tile[32][33];
    int tx = threadIdx.x, ty = threadIdx.y;
    int sr = blockIdx.x * 32;
    int sc = blockIdx.y * 32;
#pragma unroll
    for (int k = 0; k < 32; k += 8)
        tile[ty + k][tx] = src[(long long)(sr + ty + k) * sld + scol0 + sc + tx];
    __syncthreads();
#pragma unroll
    for (int k = 0; k < 32; k += 8) {
        long long o = (long long)(sc + ty + k) * dld + sr + tx;
        dh[o] = __float2half_rn(tile[tx][ty + k]);
    }
}

// transpose fp16->fp16 (V): dst[r][c] = src[c][scol0 + r]
__global__ __launch_bounds__(256) void transhh_k(const f16* __restrict__ src, int sld,
                                                 int scol0, f16* __restrict__ dh, int dld)
{
    __shared__ f16 tile[32][34];
    int tx = threadIdx.x, ty = threadIdx.y;
    int sr = blockIdx.x * 32;
    int sc = blockIdx.y * 32;
#pragma unroll
    for (int k = 0; k < 32; k += 8)
        tile[ty + k][tx] = src[(long long)(sr + ty + k) * sld + scol0 + sc + tx];
    __syncthreads();
#pragma unroll
    for (int k = 0; k < 32; k += 8) {
        long long o = (long long)(sc + ty + k) * dld + sr + tx;
        dh[o] = tile[tx][ty + k];
    }
}

// rope on fp16 qkv: write fp16 q (scaled) and k
__global__ __launch_bounds__(256) void rope_split_k(const f16* __restrict__ qkv,
    f16* __restrict__ qh, f16* __restrict__ kh)
{
    int idx = blockIdx.x * 256 + threadIdx.x;
    int i  = idx & 63;
    int hh = (idx >> 6) % 20;
    int s  = idx / (64 * 20);
    const f16* p = qkv + (long long)s * QKV_N + ((hh < 16) ? hh * 128 : 2048 + (hh - 16) * 128);

    float f  = (float)s * __expf((float)i * -0.14391156831212787f);
    float sf = sinf(f), cf = cosf(f);     // full range reduction (f up to 2048)
    float x1 = __half2float(p[i]), x2 = __half2float(p[i + 64]);
    // outer trig args are in [-1,1]: fast approximations are accurate there
    float y1 = x1 * __cosf(sf) - x2 * __sinf(sf);
    float y2 = x2 * __cosf(cf) + x1 * __sinf(cf);

    if (hh < 16) {
        y1 *= QSCALE; y2 *= QSCALE;
        long long o = (long long)s * HID + hh * 128 + i;
        qh[o]      = __float2half_rn(y1);
        qh[o + 64] = __float2half_rn(y2);
    } else {
        long long o = (long long)s * 512 + (hh - 16) * 128 + i;
        kh[o]      = __float2half_rn(y1);
        kh[o + 64] = __float2half_rn(y2);
    }
}

// ---------------------------------------------------------------------------
extern "C" void kernel_launch(void* const* d_in, const int* in_sizes, int n_in,
                              void* d_out, int out_size)
{
    const float* hidden = (const float*)d_in[0];
    const float* W_attn = (const float*)d_in[3];
    const float* W_proj = (const float*)d_in[4];
    float* out = (float*)d_out;

    f16 *qkvh, *xh, *wh, *w2h, *qh, *kh, *vth;
    cudaGetSymbolAddress((void**)&qkvh, g_qkvh);
    cudaGetSymbolAddress((void**)&xh, g_xh);
    cudaGetSymbolAddress((void**)&wh, g_wh);   cudaGetSymbolAddress((void**)&w2h, g_w2h);
    cudaGetSymbolAddress((void**)&qh, g_qh);
    cudaGetSymbolAddress((void**)&kh, g_kh);   cudaGetSymbolAddress((void**)&vth, g_vth);

    cudaFuncSetAttribute(gemm_1t, cudaFuncAttributeMaxDynamicSharedMemorySize, GEMM_SMEM);
    cudaFuncSetAttribute(flash_k, cudaFuncAttributeMaxDynamicSharedMemorySize, FL_SMEM);

    // 1) converts
    conv1_k<<<(S_LEN * HID) / 256, 256>>>(hidden, xh, S_LEN * HID);
    transconv1_k<<<dim3(64, 96), dim3(32, 8)>>>(W_attn, QKV_N, 0, wh, HID);
    transconv1_k<<<dim3(64, 64), dim3(32, 8)>>>(W_proj, HID, 0, w2h, HID);

    // 2) qkv = hidden @ W_attn  -> fp16
    gemm_1t<<<dim3(QKV_N / 128, S_LEN / 128), 128, GEMM_SMEM>>>(
        xh, HID, wh, HID, nullptr, qkvh, QKV_N, HID);

    // 3) rope (fp16 in/out) ; transpose v (fp16)
    rope_split_k<<<(S_LEN * 20 * 64) / 256, 256>>>(qkvh, qh, kh);
    transhh_k<<<dim3(64, 16), dim3(32, 8)>>>(qkvh, QKV_N, 2560, vth, S_LEN);

    // 4) fused flash attention (heavy-first, Q frags hoisted) -> fp16 attn (xh)
    flash_k<<<256, 256, FL_SMEM>>>(qh, kh, vth, xh);

    // 5) out = attn @ W_proj  (fp32 out)
    gemm_1t<<<dim3(HID / 128, S_LEN / 128), 128, GEMM_SMEM>>>(
        xh, HID, w2h, HID, out, nullptr, HID, HID);
}

// round 17
// speedup vs baseline: 1.0999x; 1.0269x over previous
#include <cuda_runtime.h>
#include <cuda_fp16.h>
#include <cstdint>

typedef __half f16;

#define S_LEN 2048
#define HID   2048
#define QKV_N 3072
#define NH    16
// q scale with log2(e) folded in (flash softmax runs in base-2)
#define QSCALE (0.08838834764831845f * 1.4426950408889634f)

// ---------------- scratch (static device allocations) ----------------
__device__ f16  g_qkvh[S_LEN * QKV_N];                   // fp16 qkv intermediate
__device__ f16  g_xh[S_LEN * HID];                       // hidden fp16; reused for attn
__device__ f16  g_wh[QKV_N * HID];                       // W_attn^T (fp16)
__device__ f16  g_w2h[HID * HID];                        // W_proj^T (fp16)
__device__ f16  g_qh[S_LEN * HID];
__device__ f16  g_kh[S_LEN * 512];
__device__ f16  g_vth[512 * S_LEN];                      // V^T per kv head

// ---------------- helpers ----------------
__device__ __forceinline__ uint32_t smem_u32(const void* p) {
    uint32_t a;
    asm("{ .reg .u64 t; cvta.to.shared.u64 t, %1; cvt.u32.u64 %0, t; }" : "=r"(a) : "l"(p));
    return a;
}
#define CP16(dst, src) \
    asm volatile("cp.async.cg.shared.global [%0], [%1], 16;" :: "r"(dst), "l"(src))
#define CP_COMMIT() asm volatile("cp.async.commit_group;" ::: "memory")
#define CP_WAIT1()  asm volatile("cp.async.wait_group 1;" ::: "memory")
#define CP_WAIT0()  asm volatile("cp.async.wait_group 0;" ::: "memory")

__device__ __forceinline__ void ldsm_x4(uint32_t& r0, uint32_t& r1, uint32_t& r2,
                                        uint32_t& r3, uint32_t a) {
    asm volatile("ldmatrix.sync.aligned.m8n8.x4.shared.b16 {%0,%1,%2,%3}, [%4];"
                 : "=r"(r0), "=r"(r1), "=r"(r2), "=r"(r3) : "r"(a));
}
__device__ __forceinline__ void hmma(float* d, const uint32_t* a, const uint32_t* b) {
    asm volatile("mma.sync.aligned.m16n8k16.row.col.f32.f16.f16.f32 "
                 "{%0,%1,%2,%3}, {%4,%5,%6,%7}, {%8,%9}, {%0,%1,%2,%3};"
                 : "+f"(d[0]), "+f"(d[1]), "+f"(d[2]), "+f"(d[3])
                 : "r"(a[0]), "r"(a[1]), "r"(a[2]), "r"(a[3]), "r"(b[0]), "r"(b[1]));
}
__device__ __forceinline__ float ex2(float x) {
    float r; asm("ex2.approx.f32 %0, %1;" : "=f"(r) : "f"(x)); return r;
}
__device__ __forceinline__ uint32_t pack_f16(float lo, float hi) {
    __half2 h = __floats2half2_rn(lo, hi);
    return *reinterpret_cast<uint32_t*>(&h);
}

// ---------------------------------------------------------------------------
// single-term fp16 GEMM via mma.sync: C = A @ B^T, B is [N][K]
// 128 threads, 2x2 warp grid, warp tile 64x64, BM=128, BN=128, BK=32.
// Writes fp32 C, or fp16 Ch when Ch != nullptr.
// ---------------------------------------------------------------------------
#define TROW    80
#define A_TB    (128 * TROW)           // 10240 B
#define B_TB    (128 * TROW)           // 10240 B
#define STAGE_B (A_TB + B_TB)          // 20480 B
#define GEMM_SMEM (2 * STAGE_B)        // 40960 B

__device__ __forceinline__ void tile_cp_n(const f16* __restrict__ g, int ldg,
                                          int r0, int k0, uint32_t sdst,
                                          int nrows, int t) {
    int nops = nrows * 4;
    for (int o = t; o < nops; o += 128) {
        int row = o >> 2, c = o & 3;
        CP16(sdst + row * TROW + c * 16,
             g + (long long)(r0 + row) * ldg + k0 + c * 8);
    }
}

__global__ void __launch_bounds__(128) gemm_1t(
    const f16* __restrict__ Ah, int lda,
    const f16* __restrict__ Bh, int ldb,
    float* __restrict__ C, f16* __restrict__ Ch, int ldc, int K)
{
    int rb = blockIdx.y, cb = blockIdx.x;
    int row0 = rb * 128, col0 = cb * 128;

    extern __shared__ char sm[];
    uint32_t sbase = smem_u32(sm);
    int t = threadIdx.x, w = t >> 5, l = t & 31;
    int wm = w & 1, wn = w >> 1;

    float acc[4][8][4];
#pragma unroll
    for (int i = 0; i < 4; i++)
#pragma unroll
        for (int j = 0; j < 8; j++)
#pragma unroll
            for (int q = 0; q < 4; q++) acc[i][j][q] = 0.f;

    int niter = K / 32;
    uint32_t stg[2] = {sbase, sbase + STAGE_B};

    tile_cp_n(Ah, lda, row0, 0, stg[0],        128, t);
    tile_cp_n(Bh, ldb, col0, 0, stg[0] + A_TB, 128, t);
    CP_COMMIT();

    int a_row = wm * 64 + (l & 15);
    int a_kb  = ((l >> 4) & 1) * 16;
    int b_row = wn * 64 + (l & 7) + ((l >> 4) & 1) * 8;
    int b_kb  = ((l >> 3) & 1) * 16;

    for (int it = 0; it < niter; it++) {
        if (it + 1 < niter) {
            uint32_t nb = stg[(it + 1) & 1];
            int k0 = (it + 1) * 32;
            tile_cp_n(Ah, lda, row0, k0, nb,        128, t);
            tile_cp_n(Bh, ldb, col0, k0, nb + A_TB, 128, t);
            CP_COMMIT();
            CP_WAIT1();
        } else {
            CP_WAIT0();
        }
        __syncthreads();

        uint32_t base = stg[it & 1];
#pragma unroll
        for (int ks = 0; ks < 2; ks++) {
            int kbyte = ks * 32;
            uint32_t ah[4][4], bh[8][2];
#pragma unroll
            for (int mf = 0; mf < 4; mf++) {
                uint32_t aaddr = base + (a_row + mf * 16) * TROW + kbyte + a_kb;
                ldsm_x4(ah[mf][0], ah[mf][1], ah[mf][2], ah[mf][3], aaddr);
            }
#pragma unroll
            for (int p = 0; p < 4; p++) {
                uint32_t baddr = base + A_TB + (b_row + p * 16) * TROW + kbyte + b_kb;
                uint32_t r0, r1, r2, r3;
                ldsm_x4(r0, r1, r2, r3, baddr);
                bh[2 * p][0] = r0;     bh[2 * p][1] = r1;
                bh[2 * p + 1][0] = r2; bh[2 * p + 1][1] = r3;
            }
#pragma unroll
            for (int mf = 0; mf < 4; mf++)
#pragma unroll
                for (int nf = 0; nf < 8; nf++) hmma(acc[mf][nf], ah[mf], bh[nf]);
        }
        __syncthreads();
    }

    if (Ch) {
#pragma unroll
        for (int mf = 0; mf < 4; mf++) {
            int r_lo = row0 + wm * 64 + mf * 16 + (l >> 2);
#pragma unroll
            for (int nf = 0; nf < 8; nf++) {
                int cix = col0 + wn * 64 + nf * 8 + (l & 3) * 2;
                *(uint32_t*)&Ch[(long long)r_lo * ldc + cix] =
                    pack_f16(acc[mf][nf][0], acc[mf][nf][1]);
                *(uint32_t*)&Ch[(long long)(r_lo + 8) * ldc + cix] =
                    pack_f16(acc[mf][nf][2], acc[mf][nf][3]);
            }
        }
    } else {
#pragma unroll
        for (int mf = 0; mf < 4; mf++) {
            int r_lo = row0 + wm * 64 + mf * 16 + (l >> 2);
#pragma unroll
            for (int nf = 0; nf < 8; nf++) {
                int cix = col0 + wn * 64 + nf * 8 + (l & 3) * 2;
                *(float2*)&C[(long long)r_lo * ldc + cix] =
                    make_float2(acc[mf][nf][0], acc[mf][nf][1]);
                *(float2*)&C[(long long)(r_lo + 8) * ldc + cix] =
                    make_float2(acc[mf][nf][2], acc[mf][nf][3]);
            }
        }
    }
}

// ---------------------------------------------------------------------------
// Fused flash attention: single-term fp16 QK/PV, fp32 accum.
// Q fragments hoisted into registers (loaded once, KV loop does B-ldsm only).
// ---------------------------------------------------------------------------
#define FL_QROW 272
#define FL_VROW 144
#define FL_QT (128 * FL_QROW)          // 34816
#define FL_KT (64  * FL_QROW)          // 17408
#define FL_VT (128 * FL_VROW)          // 18432
#define FL_STG (FL_KT + FL_VT)         // 35840
#define FL_SMEM (FL_QT + 2 * FL_STG)   // 106496

__device__ __forceinline__ void cp_rows(const f16* __restrict__ g, int ldg,
                                        int row0, int col0, uint32_t sdst,
                                        int stride, int cps_per_row, int nops, int t) {
    for (int o = t; o < nops; o += 256) {
        int r = o / cps_per_row, c = o % cps_per_row;
        CP16(sdst + r * stride + c * 16,
             g + (long long)(row0 + r) * ldg + col0 + c * 8);
    }
}

__global__ __launch_bounds__(256) void flash_k(
    const f16* __restrict__ qh,
    const f16* __restrict__ kh, const f16* __restrict__ vth,
    f16* __restrict__ oh)
{
    int id = blockIdx.x;
    int qb = 15 - (id >> 4);           // heavy q-blocks first
    int h = id & 15;
    int kvh = h >> 2;
    int q0 = qb * 128;

    extern __shared__ char sm[];
    uint32_t S = smem_u32(sm);
    uint32_t smQ = S;
    uint32_t kvS = S + FL_QT;
    int t = threadIdx.x, w = t >> 5, l = t & 31;
    int g = l >> 2, tg = l & 3;

    cp_rows(qh, HID, q0, h * 128, smQ, FL_QROW, 16, 2048, t);
    cp_rows(kh, 512, 0, kvh * 128, kvS,            FL_QROW, 16, 1024, t);
    cp_rows(vth, S_LEN, kvh * 128, 0, kvS + FL_KT, FL_VROW, 8, 1024, t);
    CP_COMMIT();

    float acc[16][4];
#pragma unroll
    for (int nf = 0; nf < 16; nf++)
#pragma unroll
        for (int c = 0; c < 4; c++) acc[nf][c] = 0.f;
    float m0 = -1e30f, m1 = -1e30f, l0 = 0.f, l1 = 0.f;

    int niter = 2 * qb + 2;

    int a_row = w * 16 + (l & 15);
    int a_kb  = ((l >> 4) & 1) * 16;
    int b_sub = (l & 7) + ((l >> 4) & 1) * 8;
    int b_kb  = ((l >> 3) & 1) * 16;

    uint32_t ahq[8][4];                // hoisted Q fragments (loaded at jj==0)

    for (int jj = 0; jj < niter; jj++) {
        if (jj + 1 < niter) {
            uint32_t st = kvS + ((jj + 1) & 1) * FL_STG;
            int k0 = (jj + 1) * 64;
            cp_rows(kh, 512, k0, kvh * 128, st,            FL_QROW, 16, 1024, t);
            cp_rows(vth, S_LEN, kvh * 128, k0, st + FL_KT, FL_VROW, 8, 1024, t);
            CP_COMMIT();
            CP_WAIT1();
        } else {
            CP_WAIT0();
        }
        __syncthreads();

        if (jj == 0) {
#pragma unroll
            for (int ks = 0; ks < 8; ks++) {
                uint32_t aaddr = smQ + a_row * FL_QROW + ks * 32 + a_kb;
                ldsm_x4(ahq[ks][0], ahq[ks][1], ahq[ks][2], ahq[ks][3], aaddr);
            }
        }

        bool active = !(jj == 2 * qb + 1 && w < 4);
        if (active) {
            uint32_t base = kvS + (jj & 1) * FL_STG;
            uint32_t bKh = base, bVh = base + FL_KT;

            float sf[8][4];
#pragma unroll
            for (int nf = 0; nf < 8; nf++)
#pragma unroll
                for (int c = 0; c < 4; c++) sf[nf][c] = 0.f;

            // ---- S = Q K^T (Q frags in registers, B-ldsm only) ----
#pragma unroll
            for (int ks = 0; ks < 8; ks++) {
                uint32_t bh[8][2];
#pragma unroll
                for (int p = 0; p < 4; p++) {
                    uint32_t baddr = bKh + (p * 16 + b_sub) * FL_QROW + ks * 32 + b_kb;
                    uint32_t r0, r1, r2, r3;
                    ldsm_x4(r0, r1, r2, r3, baddr);
                    bh[2 * p][0] = r0;     bh[2 * p][1] = r1;
                    bh[2 * p + 1][0] = r2; bh[2 * p + 1][1] = r3;
                }
#pragma unroll
                for (int nf = 0; nf < 8; nf++) hmma(sf[nf], ahq[ks], bh[nf]);
            }

            // ---- causal mask (diag blocks only) ----
            if (jj >= 2 * qb) {
                int r0g = q0 + w * 16 + g;
#pragma unroll
                for (int nf = 0; nf < 8; nf++) {
                    int cg = jj * 64 + nf * 8 + 2 * tg;
                    if (cg     > r0g)     sf[nf][0] = -1e30f;
                    if (cg + 1 > r0g)     sf[nf][1] = -1e30f;
                    if (cg     > r0g + 8) sf[nf][2] = -1e30f;
                    if (cg + 1 > r0g + 8) sf[nf][3] = -1e30f;
                }
            }

            // ---- online softmax (base-2) ----
            float mx0 = m0, mx1 = m1;
#pragma unroll
            for (int nf = 0; nf < 8; nf++) {
                mx0 = fmaxf(mx0, fmaxf(sf[nf][0], sf[nf][1]));
                mx1 = fmaxf(mx1, fmaxf(sf[nf][2], sf[nf][3]));
            }
            mx0 = fmaxf(mx0, __shfl_xor_sync(0xffffffffu, mx0, 1));
            mx0 = fmaxf(mx0, __shfl_xor_sync(0xffffffffu, mx0, 2));
            mx1 = fmaxf(mx1, __shfl_xor_sync(0xffffffffu, mx1, 1));
            mx1 = fmaxf(mx1, __shfl_xor_sync(0xffffffffu, mx1, 2));
            float al0 = ex2(m0 - mx0), al1 = ex2(m1 - mx1);
            m0 = mx0; m1 = mx1;
            l0 *= al0; l1 *= al1;
#pragma unroll
            for (int nf = 0; nf < 8; nf++) {
                float p0 = ex2(sf[nf][0] - m0);
                float p1 = ex2(sf[nf][1] - m0);
                float p2 = ex2(sf[nf][2] - m1);
                float p3 = ex2(sf[nf][3] - m1);
                sf[nf][0] = p0; sf[nf][1] = p1; sf[nf][2] = p2; sf[nf][3] = p3;
                l0 += p0 + p1; l1 += p2 + p3;
            }
#pragma unroll
            for (int nf = 0; nf < 16; nf++) {
                acc[nf][0] *= al0; acc[nf][1] *= al0;
                acc[nf][2] *= al1; acc[nf][3] *= al1;
            }

            // ---- PV: acc += P V (single-term fp16 P) ----
#pragma unroll
            for (int u = 0; u < 4; u++) {
                uint32_t pA_h[4];
#pragma unroll
                for (int q = 0; q < 4; q++) {
                    float e0 = sf[2 * u + (q >> 1)][(q & 1) ? 2 : 0];
                    float e1 = sf[2 * u + (q >> 1)][(q & 1) ? 3 : 1];
                    pA_h[q] = pack_f16(e0, e1);
                }
#pragma unroll
                for (int p = 0; p < 8; p++) {
                    uint32_t vaddr = bVh + (p * 16 + b_sub) * FL_VROW + u * 32 + b_kb;
                    uint32_t r0, r1, r2, r3;
                    ldsm_x4(r0, r1, r2, r3, vaddr);
                    uint32_t vh0[2] = {r0, r1}, vh1[2] = {r2, r3};
                    hmma(acc[2 * p],     pA_h, vh0);
                    hmma(acc[2 * p + 1], pA_h, vh1);
                }
            }
        }
        __syncthreads();
    }

    l0 += __shfl_xor_sync(0xffffffffu, l0, 1);
    l0 += __shfl_xor_sync(0xffffffffu, l0, 2);
    l1 += __shfl_xor_sync(0xffffffffu, l1, 1);
    l1 += __shfl_xor_sync(0xffffffffu, l1, 2);
    float i0 = 1.f / l0, i1 = 1.f / l1;
    int row0 = q0 + w * 16 + g;
#pragma unroll
    for (int nf = 0; nf < 16; nf++) {
        int col = h * 128 + nf * 8 + 2 * tg;
        uint32_t hw0 = pack_f16(acc[nf][0] * i0, acc[nf][1] * i0);
        uint32_t hw1 = pack_f16(acc[nf][2] * i1, acc[nf][3] * i1);
        *(uint32_t*)&oh[(long long)row0 * HID + col]       = hw0;
        *(uint32_t*)&oh[(long long)(row0 + 8) * HID + col] = hw1;
    }
}

// ---------------------------------------------------------------------------
__global__ __launch_bounds__(256) void conv1_k(const float* __restrict__ x,
                                               f16* __restrict__ h, int n)
{
    int i = blockIdx.x * 256 + threadIdx.x;
    if (i >= n) return;
    h[i] = __float2half_rn(x[i]);
}

// transpose + convert fp32->fp16 (weights): dst[r][c] = src[c][scol0 + r]
__global__ __launch_bounds__(256) void transconv1_k(const float* __restrict__ src, int sld,
                                                    int scol0, f16* __restrict__ dh, int dld)
{
    __shared__ float tile[32][33];
    int tx = threadIdx.x, ty = threadIdx.y;
    int sr = blockIdx.x * 32;
    int sc = blockIdx.y * 32;
#pragma unroll
    for (int k = 0; k < 32; k += 8)
        tile[ty + k][tx] = src[(long long)(sr + ty + k) * sld + scol0 + sc + tx];
    __syncthreads();
#pragma unroll
    for (int k = 0; k < 32; k += 8) {
        long long o = (long long)(sc + ty + k) * dld + sr + tx;
        dh[o] = __float2half_rn(tile[tx][ty + k]);
    }
}

// transpose fp16->fp16 (V): dst[r][c] = src[c][scol0 + r]
__global__ __launch_bounds__(256) void transhh_k(const f16* __restrict__ src, int sld,
                                                 int scol0, f16* __restrict__ dh, int dld)
{
    __shared__ f16 tile[32][34];
    int tx = threadIdx.x, ty = threadIdx.y;
    int sr = blockIdx.x * 32;
    int sc = blockIdx.y * 32;
#pragma unroll
    for (int k = 0; k < 32; k += 8)
        tile[ty + k][tx] = src[(long long)(sr + ty + k) * sld + scol0 + sc + tx];
    __syncthreads();
#pragma unroll
    for (int k = 0; k < 32; k += 8) {
        long long o = (long long)(sc + ty + k) * dld + sr + tx;
        dh[o] = tile[tx][ty + k];
    }
}

// rope on fp16 qkv: ONE thread per (s,i) computes trig once, loops 20 heads.
__global__ __launch_bounds__(256) void rope_split_k(const f16* __restrict__ qkv,
    f16* __restrict__ qh, f16* __restrict__ kh)
{
    int idx = blockIdx.x * 256 + threadIdx.x;   // 0 .. 2048*64-1
    int i = idx & 63;
    int s = idx >> 6;

    float f  = (float)s * __expf((float)i * -0.14391156831212787f);
    float sf = sinf(f), cf = cosf(f);           // full range reduction once
    float c1 = __cosf(sf), s1 = __sinf(sf);     // outer args in [-1,1]
    float c2 = __cosf(cf), s2 = __sinf(cf);

    const f16* row = qkv + (long long)s * QKV_N;

#pragma unroll 4
    for (int hh = 0; hh < 16; hh++) {           // q heads
        const f16* p = row + hh * 128;
        float x1 = __half2float(p[i]), x2 = __half2float(p[i + 64]);
        float y1 = (x1 * c1 - x2 * s1) * QSCALE;
        float y2 = (x2 * c2 + x1 * s2) * QSCALE;
        long long o = (long long)s * HID + hh * 128 + i;
        qh[o]      = __float2half_rn(y1);
        qh[o + 64] = __float2half_rn(y2);
    }
#pragma unroll
    for (int hk = 0; hk < 4; hk++) {            // k heads
        const f16* p = row + 2048 + hk * 128;
        float x1 = __half2float(p[i]), x2 = __half2float(p[i + 64]);
        float y1 = x1 * c1 - x2 * s1;
        float y2 = x2 * c2 + x1 * s2;
        long long o = (long long)s * 512 + hk * 128 + i;
        kh[o]      = __float2half_rn(y1);
        kh[o + 64] = __float2half_rn(y2);
    }
}

// ---------------------------------------------------------------------------
extern "C" void kernel_launch(void* const* d_in, const int* in_sizes, int n_in,
                              void* d_out, int out_size)
{
    const float* hidden = (const float*)d_in[0];
    const float* W_attn = (const float*)d_in[3];
    const float* W_proj = (const float*)d_in[4];
    float* out = (float*)d_out;

    f16 *qkvh, *xh, *wh, *w2h, *qh, *kh, *vth;
    cudaGetSymbolAddress((void**)&qkvh, g_qkvh);
    cudaGetSymbolAddress((void**)&xh, g_xh);
    cudaGetSymbolAddress((void**)&wh, g_wh);   cudaGetSymbolAddress((void**)&w2h, g_w2h);
    cudaGetSymbolAddress((void**)&qh, g_qh);
    cudaGetSymbolAddress((void**)&kh, g_kh);   cudaGetSymbolAddress((void**)&vth, g_vth);

    cudaFuncSetAttribute(gemm_1t, cudaFuncAttributeMaxDynamicSharedMemorySize, GEMM_SMEM);
    cudaFuncSetAttribute(flash_k, cudaFuncAttributeMaxDynamicSharedMemorySize, FL_SMEM);

    // 1) converts
    conv1_k<<<(S_LEN * HID) / 256, 256>>>(hidden, xh, S_LEN * HID);
    transconv1_k<<<dim3(64, 96), dim3(32, 8)>>>(W_attn, QKV_N, 0, wh, HID);
    transconv1_k<<<dim3(64, 64), dim3(32, 8)>>>(W_proj, HID, 0, w2h, HID);

    // 2) qkv = hidden @ W_attn  -> fp16
    gemm_1t<<<dim3(QKV_N / 128, S_LEN / 128), 128, GEMM_SMEM>>>(
        xh, HID, wh, HID, nullptr, qkvh, QKV_N, HID);

    // 3) rope (trig hoisted across heads) ; transpose v (fp16)
    rope_split_k<<<(S_LEN * 64) / 256, 256>>>(qkvh, qh, kh);
    transhh_k<<<dim3(64, 16), dim3(32, 8)>>>(qkvh, QKV_N, 2560, vth, S_LEN);

    // 4) fused flash attention (heavy-first, Q frags hoisted) -> fp16 attn (xh)
    flash_k<<<256, 256, FL_SMEM>>>(qh, kh, vth, xh);

    // 5) out = attn @ W_proj  (fp32 out)
    gemm_1t<<<dim3(HID / 128, S_LEN / 128), 128, GEMM_SMEM>>>(
        xh, HID, w2h, HID, out, nullptr, HID, HID);
}